// round 1
// baseline (speedup 1.0000x reference)
#include <cuda_runtime.h>
#include <cstddef>
#include <cstdint>

// Problem constants
#define S_LEN   2048
#define BATCH   2
#define DMODEL  1024
#define NHEAD   16
#define DHEAD   64
#define FFN_DIM 4096
#define NEXP    8
#define NTOK    (S_LEN*BATCH)          // 4096 tokens, t = s*BATCH + b

// ---------------- scratch (static device globals; no runtime allocation) ----
__device__ float g_ln1 [(size_t)NTOK*DMODEL];
__device__ float g_qkv [(size_t)NTOK*3*DMODEL];
__device__ float g_attn[(size_t)NTOK*DMODEL];
__device__ float g_x2  [(size_t)NTOK*DMODEL];
__device__ float g_ln2 [(size_t)NTOK*DMODEL];
__device__ float g_h1  [(size_t)NEXP*NTOK*FFN_DIM];   // 512 MB: expert hidden
__device__ float g_y   [(size_t)NEXP*NTOK*DMODEL];    // 128 MB: expert outputs
__device__ int   g_rows[NEXP*NTOK];
__device__ float g_rwgt[NEXP*NTOK];
__device__ int   g_trow[2*NTOK];
__device__ int   g_cnt [NEXP];

// ---------------- LayerNorm: one block per token row --------------------------
__global__ __launch_bounds__(256) void ln_kernel(
    const float* __restrict__ x, const float* __restrict__ g,
    const float* __restrict__ b, float* __restrict__ y)
{
    const int t   = blockIdx.x;
    const int tid = threadIdx.x;
    const float* xr = x + (size_t)t * DMODEL;
    float4 v = *(const float4*)(xr + tid * 4);
    float s  = v.x + v.y + v.z + v.w;
    float s2 = v.x*v.x + v.y*v.y + v.z*v.z + v.w*v.w;
    __shared__ float red[64];
    const int lane = tid & 31, wid = tid >> 5;
    #pragma unroll
    for (int off = 16; off; off >>= 1) {
        s  += __shfl_down_sync(0xffffffffu, s,  off);
        s2 += __shfl_down_sync(0xffffffffu, s2, off);
    }
    if (lane == 0) { red[wid] = s; red[32 + wid] = s2; }
    __syncthreads();
    if (tid == 0) {
        float ts = 0.f, ts2 = 0.f;
        #pragma unroll
        for (int i = 0; i < 8; i++) { ts += red[i]; ts2 += red[32 + i]; }
        float mean = ts * (1.f / DMODEL);
        float var  = ts2 * (1.f / DMODEL) - mean * mean;
        red[16] = mean;
        red[17] = rsqrtf(var + 1e-5f);
    }
    __syncthreads();
    const float mean = red[16], rstd = red[17];
    float4 gg = *(const float4*)(g + tid * 4);
    float4 bb = *(const float4*)(b + tid * 4);
    float4 o;
    o.x = (v.x - mean) * rstd * gg.x + bb.x;
    o.y = (v.y - mean) * rstd * gg.y + bb.y;
    o.z = (v.z - mean) * rstd * gg.z + bb.z;
    o.w = (v.w - mean) * rstd * gg.w + bb.w;
    *(float4*)(y + (size_t)t * DMODEL + tid * 4) = o;
}

// ---------------- SGEMM: C[m,n] = sum_k A[m,k] * B[n,k] (+epilogues) ----------
// 128x128x8 tile, 256 threads, 8x8 microtile.
// EPI: 0 plain, 1 +bias, 2 +bias+res, 3 silu(other)*acc, 4 rowscale*acc
// GATHER: A row index from rowsIdx; GROUPED: blockIdx.z = expert, M from cnt[e]
template<int EPI, bool GATHER, bool GROUPED>
__global__ __launch_bounds__(256) void sgemm_nt(
    const float* __restrict__ A, const float* __restrict__ Bw, float* __restrict__ C,
    const float* __restrict__ bias, const float* __restrict__ res,
    const float* __restrict__ other, const float* __restrict__ rowscale,
    const int* __restrict__ rowsIdx, const int* __restrict__ cnt,
    int M, int N, int K,
    size_t strideAe, size_t strideBe, size_t strideCe)
{
    const int e  = GROUPED ? blockIdx.z : 0;
    int Me = M;
    if (GROUPED && cnt) Me = cnt[e];
    const int m0 = blockIdx.y * 128;
    if (m0 >= Me) return;
    const int n0 = blockIdx.x * 128;

    const float* Ae = A  + (size_t)e * strideAe;
    const float* Be = Bw + (size_t)e * strideBe;
    float*       Ce = C  + (size_t)e * strideCe;

    __shared__ float As[8][128];
    __shared__ float Bs[8][128];

    const int tid = threadIdx.x;
    const int lr  = tid >> 1;          // 0..127
    const int lc  = (tid & 1) * 4;     // 0 or 4

    const int am = m0 + lr;
    const bool avalid = am < Me;
    size_t arow = 0;
    if (avalid) arow = GATHER ? (size_t)rowsIdx[e * NTOK + am] : (size_t)am;
    const float* Aptr = Ae + arow * K + lc;
    const float* Bptr = Be + (size_t)(n0 + lr) * K + lc;

    float4 av = avalid ? *(const float4*)(Aptr) : make_float4(0.f, 0.f, 0.f, 0.f);
    float4 bv = *(const float4*)(Bptr);

    float acc[8][8];
    #pragma unroll
    for (int i = 0; i < 8; i++)
        #pragma unroll
        for (int j = 0; j < 8; j++) acc[i][j] = 0.f;

    const int tx = tid & 15, ty = tid >> 4;

    for (int k0 = 0; k0 < K; k0 += 8) {
        As[lc+0][lr] = av.x; As[lc+1][lr] = av.y; As[lc+2][lr] = av.z; As[lc+3][lr] = av.w;
        Bs[lc+0][lr] = bv.x; Bs[lc+1][lr] = bv.y; Bs[lc+2][lr] = bv.z; Bs[lc+3][lr] = bv.w;
        __syncthreads();
        const int kn = k0 + 8;
        if (kn < K) {
            av = avalid ? *(const float4*)(Aptr + kn) : make_float4(0.f, 0.f, 0.f, 0.f);
            bv = *(const float4*)(Bptr + kn);
        }
        #pragma unroll
        for (int k = 0; k < 8; k++) {
            float a[8], b[8];
            #pragma unroll
            for (int i = 0; i < 8; i++) a[i] = As[k][ty*8 + i];
            #pragma unroll
            for (int j = 0; j < 8; j++) b[j] = Bs[k][tx*8 + j];
            #pragma unroll
            for (int i = 0; i < 8; i++)
                #pragma unroll
                for (int j = 0; j < 8; j++)
                    acc[i][j] += a[i] * b[j];
        }
        __syncthreads();
    }

    #pragma unroll
    for (int i = 0; i < 8; i++) {
        const int m = m0 + ty*8 + i;
        if (m >= Me) continue;
        float* crow = Ce + (size_t)m * N + n0 + tx*8;
        float out[8];
        #pragma unroll
        for (int j = 0; j < 8; j++) out[j] = acc[i][j];
        if (EPI == 1 || EPI == 2) {
            #pragma unroll
            for (int j = 0; j < 8; j++) out[j] += bias[n0 + tx*8 + j];
        }
        if (EPI == 2) {
            const float* rrow = res + (size_t)m * N + n0 + tx*8;
            #pragma unroll
            for (int j = 0; j < 8; j++) out[j] += rrow[j];
        }
        if (EPI == 3) {
            const float* orow = other + (size_t)e * strideCe + (size_t)m * N + n0 + tx*8;
            #pragma unroll
            for (int j = 0; j < 8; j++) {
                float h = orow[j];
                out[j] = (h / (1.f + __expf(-h))) * out[j];  // silu(h) * acc
            }
        }
        if (EPI == 4) {
            const float rs = rowscale[e * NTOK + m];
            #pragma unroll
            for (int j = 0; j < 8; j++) out[j] *= rs;
        }
        float4 v0 = make_float4(out[0], out[1], out[2], out[3]);
        float4 v1 = make_float4(out[4], out[5], out[6], out[7]);
        *(float4*)(crow)     = v0;
        *(float4*)(crow + 4) = v1;
    }
}

// ---------------- Flash attention (fp32, online softmax) ---------------------
// grid: (S/128, B*H), 128 threads; each thread owns one query row.
// smem: K tile [64][64], V tile [64][64], scores [128][65] (pad kills conflicts)
#define FA_SMEM ((64*64 + 64*64 + 128*65) * 4)
__global__ __launch_bounds__(128) void flash_attn_kernel(
    const float* __restrict__ qkv, float* __restrict__ out)
{
    extern __shared__ float sh[];
    float* Ks = sh;
    float* Vs = sh + 64*64;
    float* Ss = sh + 2*64*64;

    const int tid = threadIdx.x;
    const int b   = blockIdx.y & 1;        // BATCH=2
    const int h   = blockIdx.y >> 1;
    const int s_q = blockIdx.x * 128 + tid;

    const size_t qbase = ((size_t)(s_q * BATCH + b)) * (3*DMODEL) + h * DHEAD;
    float q[64];
    #pragma unroll
    for (int d = 0; d < 64; d += 4) {
        float4 v = *(const float4*)(qkv + qbase + d);
        q[d] = v.x*0.125f; q[d+1] = v.y*0.125f; q[d+2] = v.z*0.125f; q[d+3] = v.w*0.125f;
    }
    float o[64];
    #pragma unroll
    for (int d = 0; d < 64; d++) o[d] = 0.f;
    float mrow = -1e30f, lrow = 0.f;

    for (int kt = 0; kt < S_LEN; kt += 64) {
        __syncthreads();
        for (int idx = tid; idx < 64*16; idx += 128) {
            const int r = idx >> 4, c = (idx & 15) * 4;
            const size_t base = ((size_t)((kt + r) * BATCH + b)) * (3*DMODEL) + h * DHEAD + c;
            *(float4*)(Ks + r*64 + c) = *(const float4*)(qkv + DMODEL     + base);
            *(float4*)(Vs + r*64 + c) = *(const float4*)(qkv + 2*DMODEL   + base);
        }
        __syncthreads();

        float mt = -1e30f;
        for (int j = 0; j < 64; j++) {
            const float* kr = Ks + j*64;
            float acc = 0.f;
            #pragma unroll
            for (int d = 0; d < 64; d++) acc += q[d] * kr[d];
            Ss[tid*65 + j] = acc;
            mt = fmaxf(mt, acc);
        }
        const float mnew = fmaxf(mrow, mt);
        const float corr = __expf(mrow - mnew);
        lrow *= corr;
        #pragma unroll
        for (int d = 0; d < 64; d++) o[d] *= corr;
        for (int j = 0; j < 64; j++) {
            const float p = __expf(Ss[tid*65 + j] - mnew);
            lrow += p;
            const float* vr = Vs + j*64;
            #pragma unroll
            for (int d = 0; d < 64; d++) o[d] += p * vr[d];
        }
        mrow = mnew;
    }
    const float inv = 1.f / lrow;
    const size_t obase = ((size_t)(s_q * BATCH + b)) * DMODEL + h * DHEAD;
    #pragma unroll
    for (int d = 0; d < 64; d += 4) {
        float4 v = make_float4(o[d]*inv, o[d+1]*inv, o[d+2]*inv, o[d+3]*inv);
        *(float4*)(out + obase + d) = v;
    }
}

// ---------------- Router: logits, softmax, top-2, scatter into expert groups --
__global__ void zero_cnt_kernel(int* cnt) { if (threadIdx.x < NEXP) cnt[threadIdx.x] = 0; }

__global__ __launch_bounds__(256) void router_kernel(
    const float* __restrict__ h, const float* __restrict__ gw,
    float* __restrict__ logits_out,
    int* __restrict__ rows, float* __restrict__ rwgt,
    int* __restrict__ trow, int* __restrict__ cnt)
{
    const int warp = threadIdx.x >> 5, lane = threadIdx.x & 31;
    const int t = blockIdx.x * 8 + warp;
    const float* hr = h + (size_t)t * DMODEL;
    float lg[NEXP];
    #pragma unroll
    for (int e = 0; e < NEXP; e++) {
        const float* gr = gw + e * DMODEL;
        float p = 0.f;
        for (int i = lane; i < DMODEL; i += 32) p += hr[i] * gr[i];
        #pragma unroll
        for (int off = 16; off; off >>= 1) p += __shfl_xor_sync(0xffffffffu, p, off);
        lg[e] = p;
    }
    if (lane == 0) {
        if (logits_out) {
            #pragma unroll
            for (int e = 0; e < NEXP; e++) logits_out[(size_t)t * NEXP + e] = lg[e];
        }
        float mx = lg[0];
        #pragma unroll
        for (int e = 1; e < NEXP; e++) mx = fmaxf(mx, lg[e]);
        float pr[NEXP];
        #pragma unroll
        for (int e = 0; e < NEXP; e++) pr[e] = __expf(lg[e] - mx);
        int i0 = 0;
        #pragma unroll
        for (int e = 1; e < NEXP; e++) if (pr[e] > pr[i0]) i0 = e;
        int i1 = (i0 == 0) ? 1 : 0;
        #pragma unroll
        for (int e = 0; e < NEXP; e++) if (e != i0 && pr[e] > pr[i1]) i1 = e;
        const float ws = pr[i0] + pr[i1];
        const float w0 = pr[i0] / ws, w1 = pr[i1] / ws;
        int p0 = atomicAdd(&cnt[i0], 1);
        rows[i0*NTOK + p0] = t; rwgt[i0*NTOK + p0] = w0; trow[2*t + 0] = i0*NTOK + p0;
        int p1 = atomicAdd(&cnt[i1], 1);
        rows[i1*NTOK + p1] = t; rwgt[i1*NTOK + p1] = w1; trow[2*t + 1] = i1*NTOK + p1;
    }
}

// ---------------- Final combine: out = x2 + Y[row0] + Y[row1] -----------------
__global__ __launch_bounds__(256) void combine_kernel(
    const float* __restrict__ x2, const float* __restrict__ y,
    const int* __restrict__ trow, float* __restrict__ out)
{
    const int t = blockIdx.x;
    const int r0 = trow[2*t], r1 = trow[2*t + 1];
    const int i = threadIdx.x * 4;
    float4 a  = *(const float4*)(x2 + (size_t)t  * DMODEL + i);
    float4 y0 = *(const float4*)(y  + (size_t)r0 * DMODEL + i);
    float4 y1 = *(const float4*)(y  + (size_t)r1 * DMODEL + i);
    float4 o = make_float4(a.x + y0.x + y1.x, a.y + y0.y + y1.y,
                           a.z + y0.z + y1.z, a.w + y0.w + y1.w);
    *(float4*)(out + (size_t)t * DMODEL + i) = o;
}

// ---------------- host orchestration ------------------------------------------
extern "C" void kernel_launch(void* const* d_in, const int* in_sizes, int n_in,
                              void* d_out, int out_size)
{
    const float* x        = (const float*)d_in[0];
    const float* inproj_w = (const float*)d_in[1];
    const float* inproj_b = (const float*)d_in[2];
    const float* outproj_w= (const float*)d_in[3];
    const float* outproj_b= (const float*)d_in[4];
    const float* ln1_g    = (const float*)d_in[5];
    const float* ln1_b    = (const float*)d_in[6];
    const float* ln2_g    = (const float*)d_in[7];
    const float* ln2_b    = (const float*)d_in[8];
    const float* gate_w   = (const float*)d_in[9];
    const float* w1       = (const float*)d_in[10];
    const float* w2       = (const float*)d_in[11];
    const float* w3       = (const float*)d_in[12];

    float* out = (float*)d_out;
    float* logits_out = (out_size > NTOK * DMODEL) ? out + (size_t)NTOK * DMODEL : nullptr;

    float *p_ln1, *p_qkv, *p_attn, *p_x2, *p_ln2, *p_h1, *p_y, *p_rwgt;
    int *p_rows, *p_trow, *p_cnt;
    cudaGetSymbolAddress((void**)&p_ln1,  g_ln1);
    cudaGetSymbolAddress((void**)&p_qkv,  g_qkv);
    cudaGetSymbolAddress((void**)&p_attn, g_attn);
    cudaGetSymbolAddress((void**)&p_x2,   g_x2);
    cudaGetSymbolAddress((void**)&p_ln2,  g_ln2);
    cudaGetSymbolAddress((void**)&p_h1,   g_h1);
    cudaGetSymbolAddress((void**)&p_y,    g_y);
    cudaGetSymbolAddress((void**)&p_rwgt, g_rwgt);
    cudaGetSymbolAddress((void**)&p_rows, g_rows);
    cudaGetSymbolAddress((void**)&p_trow, g_trow);
    cudaGetSymbolAddress((void**)&p_cnt,  g_cnt);

    // 1. LN1
    ln_kernel<<<NTOK, 256>>>(x, ln1_g, ln1_b, p_ln1);

    // 2. QKV = ln1 @ W_in^T + b   [4096, 3072]
    sgemm_nt<1, false, false><<<dim3(3*DMODEL/128, NTOK/128), 256>>>(
        p_ln1, inproj_w, p_qkv, inproj_b, nullptr, nullptr, nullptr, nullptr, nullptr,
        NTOK, 3*DMODEL, DMODEL, 0, 0, 0);

    // 3. Flash attention
    cudaFuncSetAttribute(flash_attn_kernel,
                         cudaFuncAttributeMaxDynamicSharedMemorySize, FA_SMEM);
    flash_attn_kernel<<<dim3(S_LEN/128, BATCH*NHEAD), 128, FA_SMEM>>>(p_qkv, p_attn);

    // 4. x2 = x + attn @ W_out^T + b
    sgemm_nt<2, false, false><<<dim3(DMODEL/128, NTOK/128), 256>>>(
        p_attn, outproj_w, p_x2, outproj_b, x, nullptr, nullptr, nullptr, nullptr,
        NTOK, DMODEL, DMODEL, 0, 0, 0);

    // 5. LN2
    ln_kernel<<<NTOK, 256>>>(p_x2, ln2_g, ln2_b, p_ln2);

    // 6. Router: logits + top-2 + grouping
    zero_cnt_kernel<<<1, 32>>>(p_cnt);
    router_kernel<<<NTOK/8, 256>>>(p_ln2, gate_w, logits_out,
                                   p_rows, p_rwgt, p_trow, p_cnt);

    // 7. MoE expert GEMMs (grouped, gathered)
    //   h1 = T_e @ w1[e]^T
    sgemm_nt<0, true, true><<<dim3(FFN_DIM/128, NTOK/128, NEXP), 256>>>(
        p_ln2, w1, p_h1, nullptr, nullptr, nullptr, nullptr, p_rows, p_cnt,
        NTOK, FFN_DIM, DMODEL,
        0, (size_t)FFN_DIM*DMODEL, (size_t)NTOK*FFN_DIM);
    //   h1 = silu(h1) * (T_e @ w3[e]^T)   (in place)
    sgemm_nt<3, true, true><<<dim3(FFN_DIM/128, NTOK/128, NEXP), 256>>>(
        p_ln2, w3, p_h1, nullptr, nullptr, p_h1, nullptr, p_rows, p_cnt,
        NTOK, FFN_DIM, DMODEL,
        0, (size_t)FFN_DIM*DMODEL, (size_t)NTOK*FFN_DIM);
    //   Y = wgt * (h1 @ w2[e]^T)
    sgemm_nt<4, false, true><<<dim3(DMODEL/128, NTOK/128, NEXP), 256>>>(
        p_h1, w2, p_y, nullptr, nullptr, nullptr, p_rwgt, nullptr, p_cnt,
        NTOK, DMODEL, FFN_DIM,
        (size_t)NTOK*FFN_DIM, (size_t)DMODEL*FFN_DIM, (size_t)NTOK*DMODEL);

    // 8. out = x2 + Y[slot0] + Y[slot1]
    combine_kernel<<<NTOK, 256>>>(p_x2, p_y, p_trow, out);
}

// round 3
// speedup vs baseline: 2.2863x; 2.2863x over previous
#include <cuda_runtime.h>
#include <cstddef>
#include <cstdint>

// Problem constants
#define S_LEN   2048
#define BATCH   2
#define DMODEL  1024
#define NHEAD   16
#define DHEAD   64
#define FFN_DIM 4096
#define NEXP    8
#define NTOK    (S_LEN*BATCH)          // 4096 tokens, t = s*BATCH + b

// ---------------- scratch (static device globals; no runtime allocation) ----
__device__ float g_ln1 [(size_t)NTOK*DMODEL];
__device__ float g_qkv [(size_t)NTOK*3*DMODEL];
__device__ float g_attn[(size_t)NTOK*DMODEL];
__device__ float g_x2  [(size_t)NTOK*DMODEL];
__device__ float g_ln2 [(size_t)NTOK*DMODEL];
__device__ float g_h1  [(size_t)NEXP*NTOK*FFN_DIM];   // expert hidden
__device__ float g_y   [(size_t)NEXP*NTOK*DMODEL];    // expert outputs
__device__ int   g_rows[NEXP*NTOK];
__device__ float g_rwgt[NEXP*NTOK];
__device__ int   g_trow[2*NTOK];
__device__ int   g_cnt [NEXP];

// ---------------- helpers ----------------------------------------------------
__device__ __forceinline__ uint32_t smem_u32(const void* p) {
    return (uint32_t)__cvta_generic_to_shared(p);
}
#define CP_ASYNC16(dst, src) \
    asm volatile("cp.async.cg.shared.global [%0], [%1], 16;\n" :: "r"(dst), "l"(src))
#define CP_COMMIT()  asm volatile("cp.async.commit_group;\n")
#define CP_WAIT1()   asm volatile("cp.async.wait_group 1;\n")

__device__ __forceinline__ void mma_tf32(float c[4], const uint32_t a[4], const uint32_t b[2]) {
    asm volatile(
        "mma.sync.aligned.m16n8k8.row.col.f32.tf32.tf32.f32 "
        "{%0,%1,%2,%3}, {%4,%5,%6,%7}, {%8,%9}, {%0,%1,%2,%3};"
        : "+f"(c[0]), "+f"(c[1]), "+f"(c[2]), "+f"(c[3])
        : "r"(a[0]), "r"(a[1]), "r"(a[2]), "r"(a[3]), "r"(b[0]), "r"(b[1]));
}

// ---------------- LayerNorm: one block per token row --------------------------
__global__ __launch_bounds__(256) void ln_kernel(
    const float* __restrict__ x, const float* __restrict__ g,
    const float* __restrict__ b, float* __restrict__ y)
{
    const int t   = blockIdx.x;
    const int tid = threadIdx.x;
    const float* xr = x + (size_t)t * DMODEL;
    float4 v = *(const float4*)(xr + tid * 4);
    float s  = v.x + v.y + v.z + v.w;
    float s2 = v.x*v.x + v.y*v.y + v.z*v.z + v.w*v.w;
    __shared__ float red[64];
    const int lane = tid & 31, wid = tid >> 5;
    #pragma unroll
    for (int off = 16; off; off >>= 1) {
        s  += __shfl_down_sync(0xffffffffu, s,  off);
        s2 += __shfl_down_sync(0xffffffffu, s2, off);
    }
    if (lane == 0) { red[wid] = s; red[32 + wid] = s2; }
    __syncthreads();
    if (tid == 0) {
        float ts = 0.f, ts2 = 0.f;
        #pragma unroll
        for (int i = 0; i < 8; i++) { ts += red[i]; ts2 += red[32 + i]; }
        float mean = ts * (1.f / DMODEL);
        float var  = ts2 * (1.f / DMODEL) - mean * mean;
        red[16] = mean;
        red[17] = rsqrtf(var + 1e-5f);
    }
    __syncthreads();
    const float mean = red[16], rstd = red[17];
    float4 gg = *(const float4*)(g + tid * 4);
    float4 bb = *(const float4*)(b + tid * 4);
    float4 o;
    o.x = (v.x - mean) * rstd * gg.x + bb.x;
    o.y = (v.y - mean) * rstd * gg.y + bb.y;
    o.z = (v.z - mean) * rstd * gg.z + bb.z;
    o.w = (v.w - mean) * rstd * gg.w + bb.w;
    *(float4*)(y + (size_t)t * DMODEL + tid * 4) = o;
}

// ---------------- TF32 tensor-core GEMM --------------------------------------
// C[m,n] = sum_k A[m,k] * B[n,k]  (row-major A, row-major B as [N][K])
// 128x128 tile, BK=16, 3-stage cp.async pipeline, 256 threads (2x4 warps),
// each warp 64x32 via m16n8k8 tf32 mma (4 m-frags x 4 n-frags x 2 k-steps).
// smem: [row][20] layout -> all fragment LDS conflict-free.
// EPI: 0 plain, 1 +bias, 2 +bias+res, 3 silu(other)*acc, 4 rowscale*acc
#define GEMM_SMEM (3 * 2 * 2560 * 4)

template<int EPI, bool GATHER, bool GROUPED>
__global__ __launch_bounds__(256) void gemm_tf32(
    const float* __restrict__ A, const float* __restrict__ Bw, float* __restrict__ C,
    const float* __restrict__ bias, const float* __restrict__ res,
    const float* __restrict__ other, const float* __restrict__ rowscale,
    const int* __restrict__ rowsIdx, const int* __restrict__ cnt,
    int M, int N, int K,
    size_t strideAe, size_t strideBe, size_t strideCe)
{
    const int e  = GROUPED ? blockIdx.z : 0;
    int Me = M;
    if (GROUPED && cnt) Me = cnt[e];
    const int m0 = blockIdx.y * 128;
    if (m0 >= Me) return;
    const int n0 = blockIdx.x * 128;

    const float* Ae = A  + (size_t)e * strideAe;
    const float* Be = Bw + (size_t)e * strideBe;
    float*       Ce = C  + (size_t)e * strideCe;

    extern __shared__ float sh[];
    float* Asm = sh;                 // [3][128][20]
    float* Bsm = sh + 3 * 2560;      // [3][128][20]

    const int tid  = threadIdx.x;
    const int lane = tid & 31, wid = tid >> 5;
    const int wm = wid >> 2, wn = wid & 3;   // warp grid 2 x 4
    const int q  = lane >> 2, r = lane & 3;

    // ---- staging: each thread owns 2 A-rows and 2 B-rows, one 16B chunk each
    const int ldRow = tid >> 2;              // 0..63
    const int c4    = (tid & 3) << 2;        // float offset 0,4,8,12
    const int amr0 = m0 + ldRow, amr1 = m0 + 64 + ldRow;
    size_t ar0, ar1;
    if (GATHER) {
        ar0 = (size_t)rowsIdx[e * NTOK + (amr0 < Me ? amr0 : Me - 1)];
        ar1 = (size_t)rowsIdx[e * NTOK + (amr1 < Me ? amr1 : Me - 1)];
    } else {
        ar0 = (size_t)(amr0 < Me ? amr0 : Me - 1);
        ar1 = (size_t)(amr1 < Me ? amr1 : Me - 1);
    }
    const float* aSrc0 = Ae + ar0 * K + c4;
    const float* aSrc1 = Ae + ar1 * K + c4;
    const float* bSrc0 = Be + (size_t)(n0 + ldRow) * K + c4;
    const float* bSrc1 = Be + (size_t)(n0 + 64 + ldRow) * K + c4;

    const uint32_t stageB = 2560 * 4;
    const uint32_t sA  = smem_u32(Asm) + (uint32_t)(ldRow * 20 + c4) * 4;
    const uint32_t sA1 = sA + 64 * 20 * 4;
    const uint32_t sB  = smem_u32(Bsm) + (uint32_t)(ldRow * 20 + c4) * 4;
    const uint32_t sB1 = sB + 64 * 20 * 4;

    const int KT = K >> 4;

    // prefetch stages 0,1
    #pragma unroll
    for (int s = 0; s < 2; s++) {
        if (s < KT) {
            const int k0 = s << 4;
            const uint32_t off = s * stageB;
            CP_ASYNC16(sA  + off, aSrc0 + k0);
            CP_ASYNC16(sA1 + off, aSrc1 + k0);
            CP_ASYNC16(sB  + off, bSrc0 + k0);
            CP_ASYNC16(sB1 + off, bSrc1 + k0);
        }
        CP_COMMIT();
    }

    float acc[4][4][4];
    #pragma unroll
    for (int i = 0; i < 4; i++)
        #pragma unroll
        for (int j = 0; j < 4; j++)
            #pragma unroll
            for (int k = 0; k < 4; k++) acc[i][j][k] = 0.f;

    const int aoff = (wm * 64 + q) * 20 + r;
    const int boff = (wn * 32 + q) * 20 + r;

    int rs = 0;
    for (int kt = 0; kt < KT; kt++) {
        CP_WAIT1();
        __syncthreads();

        const int kp = kt + 2;
        if (kp < KT) {
            const int k0 = kp << 4;
            const uint32_t off = (uint32_t)(kp % 3) * stageB;
            CP_ASYNC16(sA  + off, aSrc0 + k0);
            CP_ASYNC16(sA1 + off, aSrc1 + k0);
            CP_ASYNC16(sB  + off, bSrc0 + k0);
            CP_ASYNC16(sB1 + off, bSrc1 + k0);
        }
        CP_COMMIT();

        const float* As_s = Asm + rs * 2560;
        const float* Bs_s = Bsm + rs * 2560;
        #pragma unroll
        for (int ks = 0; ks < 2; ks++) {
            uint32_t a[4][4], b[4][2];
            #pragma unroll
            for (int mt = 0; mt < 4; mt++) {
                const int base = aoff + mt * 320 + ks * 8;
                a[mt][0] = __float_as_uint(As_s[base]);
                a[mt][1] = __float_as_uint(As_s[base + 160]);
                a[mt][2] = __float_as_uint(As_s[base + 4]);
                a[mt][3] = __float_as_uint(As_s[base + 164]);
            }
            #pragma unroll
            for (int nt = 0; nt < 4; nt++) {
                const int base = boff + nt * 160 + ks * 8;
                b[nt][0] = __float_as_uint(Bs_s[base]);
                b[nt][1] = __float_as_uint(Bs_s[base + 4]);
            }
            #pragma unroll
            for (int mt = 0; mt < 4; mt++)
                #pragma unroll
                for (int nt = 0; nt < 4; nt++)
                    mma_tf32(acc[mt][nt], a[mt], b[nt]);
        }
        rs++; if (rs == 3) rs = 0;
    }

    // ---- epilogue
    #pragma unroll
    for (int mt = 0; mt < 4; mt++) {
        #pragma unroll
        for (int h2 = 0; h2 < 2; h2++) {
            const int m = m0 + wm * 64 + mt * 16 + q + h2 * 8;
            if (m >= Me) continue;
            float* crow = Ce + (size_t)m * N + n0 + wn * 32;
            float rsw = 1.f;
            if (EPI == 4) rsw = rowscale[e * NTOK + m];
            #pragma unroll
            for (int nt = 0; nt < 4; nt++) {
                const int col = nt * 8 + 2 * r;
                float v0 = acc[mt][nt][h2 * 2 + 0];
                float v1 = acc[mt][nt][h2 * 2 + 1];
                if (EPI == 1 || EPI == 2) {
                    v0 += bias[n0 + wn * 32 + col];
                    v1 += bias[n0 + wn * 32 + col + 1];
                }
                if (EPI == 2) {
                    const float* rrow = res + (size_t)m * N + n0 + wn * 32;
                    v0 += rrow[col]; v1 += rrow[col + 1];
                }
                if (EPI == 3) {
                    const float* orow = other + (size_t)e * strideCe + (size_t)m * N + n0 + wn * 32;
                    const float h0 = orow[col], h1v = orow[col + 1];
                    v0 = (h0  / (1.f + __expf(-h0 ))) * v0;
                    v1 = (h1v / (1.f + __expf(-h1v))) * v1;
                }
                if (EPI == 4) { v0 *= rsw; v1 *= rsw; }
                *(float2*)(crow + col) = make_float2(v0, v1);
            }
        }
    }
}

// ---------------- Flash attention (fp32, online softmax) ---------------------
#define FA_SMEM ((64*64 + 64*64 + 128*65) * 4)
__global__ __launch_bounds__(128) void flash_attn_kernel(
    const float* __restrict__ qkv, float* __restrict__ out)
{
    extern __shared__ float sh[];
    float* Ks = sh;
    float* Vs = sh + 64*64;
    float* Ss = sh + 2*64*64;

    const int tid = threadIdx.x;
    const int b   = blockIdx.y & 1;
    const int h   = blockIdx.y >> 1;
    const int s_q = blockIdx.x * 128 + tid;

    const size_t qbase = ((size_t)(s_q * BATCH + b)) * (3*DMODEL) + h * DHEAD;
    float q[64];
    #pragma unroll
    for (int d = 0; d < 64; d += 4) {
        float4 v = *(const float4*)(qkv + qbase + d);
        q[d] = v.x*0.125f; q[d+1] = v.y*0.125f; q[d+2] = v.z*0.125f; q[d+3] = v.w*0.125f;
    }
    float o[64];
    #pragma unroll
    for (int d = 0; d < 64; d++) o[d] = 0.f;
    float mrow = -1e30f, lrow = 0.f;

    for (int kt = 0; kt < S_LEN; kt += 64) {
        __syncthreads();
        for (int idx = tid; idx < 64*16; idx += 128) {
            const int rr = idx >> 4, c = (idx & 15) * 4;
            const size_t base = ((size_t)((kt + rr) * BATCH + b)) * (3*DMODEL) + h * DHEAD + c;
            *(float4*)(Ks + rr*64 + c) = *(const float4*)(qkv + DMODEL   + base);
            *(float4*)(Vs + rr*64 + c) = *(const float4*)(qkv + 2*DMODEL + base);
        }
        __syncthreads();

        float mt = -1e30f;
        for (int j = 0; j < 64; j++) {
            const float* kr = Ks + j*64;
            float acc = 0.f;
            #pragma unroll
            for (int d = 0; d < 64; d++) acc += q[d] * kr[d];
            Ss[tid*65 + j] = acc;
            mt = fmaxf(mt, acc);
        }
        const float mnew = fmaxf(mrow, mt);
        const float corr = __expf(mrow - mnew);
        lrow *= corr;
        #pragma unroll
        for (int d = 0; d < 64; d++) o[d] *= corr;
        for (int j = 0; j < 64; j++) {
            const float p = __expf(Ss[tid*65 + j] - mnew);
            lrow += p;
            const float* vr = Vs + j*64;
            #pragma unroll
            for (int d = 0; d < 64; d++) o[d] += p * vr[d];
        }
        mrow = mnew;
    }
    const float inv = 1.f / lrow;
    const size_t obase = ((size_t)(s_q * BATCH + b)) * DMODEL + h * DHEAD;
    #pragma unroll
    for (int d = 0; d < 64; d += 4) {
        float4 v = make_float4(o[d]*inv, o[d+1]*inv, o[d+2]*inv, o[d+3]*inv);
        *(float4*)(out + obase + d) = v;
    }
}

// ---------------- Router -------------------------------------------------------
__global__ void zero_cnt_kernel(int* cnt) { if (threadIdx.x < NEXP) cnt[threadIdx.x] = 0; }

__global__ __launch_bounds__(256) void router_kernel(
    const float* __restrict__ h, const float* __restrict__ gw,
    float* __restrict__ logits_out,
    int* __restrict__ rows, float* __restrict__ rwgt,
    int* __restrict__ trow, int* __restrict__ cnt)
{
    const int warp = threadIdx.x >> 5, lane = threadIdx.x & 31;
    const int t = blockIdx.x * 8 + warp;
    const float* hr = h + (size_t)t * DMODEL;
    float lg[NEXP];
    #pragma unroll
    for (int e = 0; e < NEXP; e++) {
        const float* gr = gw + e * DMODEL;
        float p = 0.f;
        for (int i = lane; i < DMODEL; i += 32) p += hr[i] * gr[i];
        #pragma unroll
        for (int off = 16; off; off >>= 1) p += __shfl_xor_sync(0xffffffffu, p, off);
        lg[e] = p;
    }
    if (lane == 0) {
        if (logits_out) {
            #pragma unroll
            for (int e = 0; e < NEXP; e++) logits_out[(size_t)t * NEXP + e] = lg[e];
        }
        float mx = lg[0];
        #pragma unroll
        for (int e = 1; e < NEXP; e++) mx = fmaxf(mx, lg[e]);
        float pr[NEXP];
        #pragma unroll
        for (int e = 0; e < NEXP; e++) pr[e] = __expf(lg[e] - mx);
        int i0 = 0;
        #pragma unroll
        for (int e = 1; e < NEXP; e++) if (pr[e] > pr[i0]) i0 = e;
        int i1 = (i0 == 0) ? 1 : 0;
        #pragma unroll
        for (int e = 0; e < NEXP; e++) if (e != i0 && pr[e] > pr[i1]) i1 = e;
        const float ws = pr[i0] + pr[i1];
        const float w0 = pr[i0] / ws, w1 = pr[i1] / ws;
        int p0 = atomicAdd(&cnt[i0], 1);
        rows[i0*NTOK + p0] = t; rwgt[i0*NTOK + p0] = w0; trow[2*t + 0] = i0*NTOK + p0;
        int p1 = atomicAdd(&cnt[i1], 1);
        rows[i1*NTOK + p1] = t; rwgt[i1*NTOK + p1] = w1; trow[2*t + 1] = i1*NTOK + p1;
    }
}

// ---------------- Final combine ------------------------------------------------
__global__ __launch_bounds__(256) void combine_kernel(
    const float* __restrict__ x2, const float* __restrict__ y,
    const int* __restrict__ trow, float* __restrict__ out)
{
    const int t = blockIdx.x;
    const int r0 = trow[2*t], r1 = trow[2*t + 1];
    const int i = threadIdx.x * 4;
    float4 a  = *(const float4*)(x2 + (size_t)t  * DMODEL + i);
    float4 y0 = *(const float4*)(y  + (size_t)r0 * DMODEL + i);
    float4 y1 = *(const float4*)(y  + (size_t)r1 * DMODEL + i);
    float4 o = make_float4(a.x + y0.x + y1.x, a.y + y0.y + y1.y,
                           a.z + y0.z + y1.z, a.w + y0.w + y1.w);
    *(float4*)(out + (size_t)t * DMODEL + i) = o;
}

// ---------------- host orchestration ------------------------------------------
extern "C" void kernel_launch(void* const* d_in, const int* in_sizes, int n_in,
                              void* d_out, int out_size)
{
    const float* x        = (const float*)d_in[0];
    const float* inproj_w = (const float*)d_in[1];
    const float* inproj_b = (const float*)d_in[2];
    const float* outproj_w= (const float*)d_in[3];
    const float* outproj_b= (const float*)d_in[4];
    const float* ln1_g    = (const float*)d_in[5];
    const float* ln1_b    = (const float*)d_in[6];
    const float* ln2_g    = (const float*)d_in[7];
    const float* ln2_b    = (const float*)d_in[8];
    const float* gate_w   = (const float*)d_in[9];
    const float* w1       = (const float*)d_in[10];
    const float* w2       = (const float*)d_in[11];
    const float* w3       = (const float*)d_in[12];

    float* out = (float*)d_out;
    float* logits_out = (out_size > NTOK * DMODEL) ? out + (size_t)NTOK * DMODEL : nullptr;

    float *p_ln1, *p_qkv, *p_attn, *p_x2, *p_ln2, *p_h1, *p_y, *p_rwgt;
    int *p_rows, *p_trow, *p_cnt;
    cudaGetSymbolAddress((void**)&p_ln1,  g_ln1);
    cudaGetSymbolAddress((void**)&p_qkv,  g_qkv);
    cudaGetSymbolAddress((void**)&p_attn, g_attn);
    cudaGetSymbolAddress((void**)&p_x2,   g_x2);
    cudaGetSymbolAddress((void**)&p_ln2,  g_ln2);
    cudaGetSymbolAddress((void**)&p_h1,   g_h1);
    cudaGetSymbolAddress((void**)&p_y,    g_y);
    cudaGetSymbolAddress((void**)&p_rwgt, g_rwgt);
    cudaGetSymbolAddress((void**)&p_rows, g_rows);
    cudaGetSymbolAddress((void**)&p_trow, g_trow);
    cudaGetSymbolAddress((void**)&p_cnt,  g_cnt);

    cudaFuncSetAttribute(gemm_tf32<1,false,false>, cudaFuncAttributeMaxDynamicSharedMemorySize, GEMM_SMEM);
    cudaFuncSetAttribute(gemm_tf32<2,false,false>, cudaFuncAttributeMaxDynamicSharedMemorySize, GEMM_SMEM);
    cudaFuncSetAttribute(gemm_tf32<0,true, true >, cudaFuncAttributeMaxDynamicSharedMemorySize, GEMM_SMEM);
    cudaFuncSetAttribute(gemm_tf32<3,true, true >, cudaFuncAttributeMaxDynamicSharedMemorySize, GEMM_SMEM);
    cudaFuncSetAttribute(gemm_tf32<4,false,true >, cudaFuncAttributeMaxDynamicSharedMemorySize, GEMM_SMEM);
    cudaFuncSetAttribute(flash_attn_kernel,        cudaFuncAttributeMaxDynamicSharedMemorySize, FA_SMEM);

    // 1. LN1
    ln_kernel<<<NTOK, 256>>>(x, ln1_g, ln1_b, p_ln1);

    // 2. QKV = ln1 @ W_in^T + b   [4096, 3072]
    gemm_tf32<1,false,false><<<dim3(3*DMODEL/128, NTOK/128), 256, GEMM_SMEM>>>(
        p_ln1, inproj_w, p_qkv, inproj_b, nullptr, nullptr, nullptr, nullptr, nullptr,
        NTOK, 3*DMODEL, DMODEL, 0, 0, 0);

    // 3. Flash attention
    flash_attn_kernel<<<dim3(S_LEN/128, BATCH*NHEAD), 128, FA_SMEM>>>(p_qkv, p_attn);

    // 4. x2 = x + attn @ W_out^T + b
    gemm_tf32<2,false,false><<<dim3(DMODEL/128, NTOK/128), 256, GEMM_SMEM>>>(
        p_attn, outproj_w, p_x2, outproj_b, x, nullptr, nullptr, nullptr, nullptr,
        NTOK, DMODEL, DMODEL, 0, 0, 0);

    // 5. LN2
    ln_kernel<<<NTOK, 256>>>(p_x2, ln2_g, ln2_b, p_ln2);

    // 6. Router
    zero_cnt_kernel<<<1, 32>>>(p_cnt);
    router_kernel<<<NTOK/8, 256>>>(p_ln2, gate_w, logits_out,
                                   p_rows, p_rwgt, p_trow, p_cnt);

    // 7. MoE expert GEMMs (grouped, gathered)
    gemm_tf32<0,true,true><<<dim3(FFN_DIM/128, NTOK/128, NEXP), 256, GEMM_SMEM>>>(
        p_ln2, w1, p_h1, nullptr, nullptr, nullptr, nullptr, p_rows, p_cnt,
        NTOK, FFN_DIM, DMODEL,
        0, (size_t)FFN_DIM*DMODEL, (size_t)NTOK*FFN_DIM);
    gemm_tf32<3,true,true><<<dim3(FFN_DIM/128, NTOK/128, NEXP), 256, GEMM_SMEM>>>(
        p_ln2, w3, p_h1, nullptr, nullptr, p_h1, nullptr, p_rows, p_cnt,
        NTOK, FFN_DIM, DMODEL,
        0, (size_t)FFN_DIM*DMODEL, (size_t)NTOK*FFN_DIM);
    gemm_tf32<4,false,true><<<dim3(DMODEL/128, NTOK/128, NEXP), 256, GEMM_SMEM>>>(
        p_h1, w2, p_y, nullptr, nullptr, nullptr, p_rwgt, nullptr, p_cnt,
        NTOK, DMODEL, FFN_DIM,
        (size_t)NTOK*FFN_DIM, (size_t)DMODEL*FFN_DIM, (size_t)NTOK*DMODEL);

    // 8. out = x2 + Y[slot0] + Y[slot1]
    combine_kernel<<<NTOK, 256>>>(p_x2, p_y, p_trow, out);
}